// round 2
// baseline (speedup 1.0000x reference)
#include <cuda_runtime.h>

#define BB 16
#define SS 2048
#define KK 16
#define LL 64
#define II 256
#define NS (BB*SS)   // 32768

#define SPB 16       // samples per emissions block
#define TPB 256

// Scratch (device globals; no allocation allowed)
__device__ float2 g_emE[NS*KK];    // (E = exp(clamp(em',-80)), em' = em - rowmax)
__device__ float  g_rowmax[NS];
__device__ float  g_invvar[KK*LL];
__device__ float  g_lvsum[KK];

// ---------------------------------------------------------------------------
// Setup: invvar = 1/(exp(logvar)+1e-8), per-state logvar sums
// ---------------------------------------------------------------------------
__global__ void setup_kernel(const float* __restrict__ prior_logvar) {
    int tid = threadIdx.x;
    if (tid < KK*LL) {
        float lv = prior_logvar[tid];
        g_invvar[tid] = 1.0f / (expf(lv) + 1e-8f);
    }
    if (tid < KK) {
        float s = 0.f;
        #pragma unroll
        for (int l = 0; l < LL; l++) s += __ldg(prior_logvar + tid*LL + l);
        g_lvsum[tid] = s;
    }
}

// ---------------------------------------------------------------------------
// Emissions: em[b,s,k] = -0.5*||d - Ws_k||^2
//            -0.5*(sum(logvar_k) + sum((z-mu_k)^2/var_k) + L*log(2pi))
// Stores (E, em') packed + rowmax for the scan.
// ---------------------------------------------------------------------------
__global__ void __launch_bounds__(TPB) emissions_kernel(
    const float* __restrict__ Y, const float* __restrict__ Z,
    const float* __restrict__ Wz, const float* __restrict__ Ws,
    const float* __restrict__ bdec, const float* __restrict__ mu)
{
    __shared__ __align__(16) float z_a[LL][SPB];      // [l][s]
    __shared__ __align__(16) float z_b[SPB][LL+4];    // [s][l] padded
    __shared__ __align__(16) float d_sh[SPB][II];
    __shared__ __align__(16) float ws_sh[KK][II+4];   // padded rows (1040B)

    int tid = threadIdx.x;
    int s0 = blockIdx.x * SPB;

    // Load z tile (both layouts)
    #pragma unroll
    for (int e = 0; e < (SPB*LL)/TPB; e++) {
        int idx = tid + TPB*e;
        int s = idx >> 6, l = idx & 63;
        float v = Z[(s0 + s)*LL + l];
        z_a[l][s] = v;
        z_b[s][l] = v;
    }
    // Load Ws tile
    #pragma unroll
    for (int e = 0; e < (KK*II)/TPB; e++) {
        int idx = tid + TPB*e;
        ws_sh[idx >> 8][idx & 255] = Ws[idx];
    }
    __syncthreads();

    // ---- Phase A: base_i = b_dec_i + sum_l z_l * Wz[l][i]; d = y - base ----
    {
        float base[SPB];
        float bd = __ldg(bdec + tid);
        #pragma unroll
        for (int s = 0; s < SPB; s++) base[s] = bd;

        #pragma unroll 4
        for (int l = 0; l < LL; l++) {
            float wz = __ldg(Wz + l*II + tid);
            const float4* zr = (const float4*)&z_a[l][0];
            float4 za = zr[0], zb = zr[1], zc = zr[2], zd = zr[3];
            base[0]  = fmaf(za.x, wz, base[0]);
            base[1]  = fmaf(za.y, wz, base[1]);
            base[2]  = fmaf(za.z, wz, base[2]);
            base[3]  = fmaf(za.w, wz, base[3]);
            base[4]  = fmaf(zb.x, wz, base[4]);
            base[5]  = fmaf(zb.y, wz, base[5]);
            base[6]  = fmaf(zb.z, wz, base[6]);
            base[7]  = fmaf(zb.w, wz, base[7]);
            base[8]  = fmaf(zc.x, wz, base[8]);
            base[9]  = fmaf(zc.y, wz, base[9]);
            base[10] = fmaf(zc.z, wz, base[10]);
            base[11] = fmaf(zc.w, wz, base[11]);
            base[12] = fmaf(zd.x, wz, base[12]);
            base[13] = fmaf(zd.y, wz, base[13]);
            base[14] = fmaf(zd.z, wz, base[14]);
            base[15] = fmaf(zd.w, wz, base[15]);
        }
        #pragma unroll
        for (int s = 0; s < SPB; s++) {
            float y = __ldg(Y + (s0 + s)*II + tid);
            d_sh[s][tid] = y - base[s];
        }
    }
    __syncthreads();

    // ---- Phase B: thread (sample, state) owns full dot products ----
    int si = tid >> 4;
    int k  = tid & 15;

    float a0 = 0.f, a1 = 0.f, a2 = 0.f, a3 = 0.f;
    const float4* dr = (const float4*)&d_sh[si][0];
    const float4* wr = (const float4*)&ws_sh[k][0];
    #pragma unroll 8
    for (int i4 = 0; i4 < II/4; i4++) {
        float4 dv = dr[i4], wv = wr[i4];
        float t0 = dv.x - wv.x; a0 = fmaf(t0, t0, a0);
        float t1 = dv.y - wv.y; a1 = fmaf(t1, t1, a1);
        float t2 = dv.z - wv.z; a2 = fmaf(t2, t2, a2);
        float t3 = dv.w - wv.w; a3 = fmaf(t3, t3, a3);
    }
    float accy = (a0 + a1) + (a2 + a3);

    float b0 = 0.f, b1 = 0.f, b2 = 0.f, b3 = 0.f;
    const float4* zr = (const float4*)&z_b[si][0];
    const float4* mr = (const float4*)(mu + k*LL);
    const float4* ir = (const float4*)(g_invvar + k*LL);
    #pragma unroll
    for (int l4 = 0; l4 < LL/4; l4++) {
        float4 zv = zr[l4];
        float4 mv = __ldg(mr + l4);
        float4 iv = __ldg(ir + l4);
        float t0 = zv.x - mv.x; b0 = fmaf(t0*t0, iv.x, b0);
        float t1 = zv.y - mv.y; b1 = fmaf(t1*t1, iv.y, b1);
        float t2 = zv.z - mv.z; b2 = fmaf(t2*t2, iv.z, b2);
        float t3 = zv.w - mv.w; b3 = fmaf(t3*t3, iv.w, b3);
    }
    float accz = (b0 + b1) + (b2 + b3);

    const float LLOG2PI = 117.62413f;  // 64 * log(2*pi)
    float em = -0.5f*accy - 0.5f*(__ldg(&g_lvsum[k]) + accz + LLOG2PI);

    // Row max over k (lanes: (s&1)*16 + k -> xor<=8 stays in 16-group)
    float m = em;
    #pragma unroll
    for (int off = 8; off; off >>= 1)
        m = fmaxf(m, __shfl_xor_sync(0xffffffffu, m, off));

    float emp = em - m;
    float E = __expf(fmaxf(emp, -80.f));

    int sample = s0 + si;
    g_emE[sample*KK + k] = make_float2(E, emp);
    if (k == 0) g_rowmax[sample] = m;
}

// ---------------------------------------------------------------------------
// Forward scan: one warp per batch. Linear-space recursion q' = (q A) ∘ E,
// exact output alpha = C + rowmax + em' + ln(s). Renorm every 16 steps.
// ---------------------------------------------------------------------------
__device__ __forceinline__ void scan_block16(
    const float2* __restrict__ buf, const float* __restrict__ rm, int base,
    float& q, float& C, const float (&acol)[KK], float lstart,
    float* __restrict__ ob, int lane, int kk)
{
    const unsigned FULL = 0xffffffffu;
    #pragma unroll
    for (int u = 0; u < 16; u++) {
        if (u == 0 && base == 0) {
            float a0 = lstart + buf[0].y + rm[0];
            if (lane < 16) ob[kk] = a0;
            q = __expf(fmaxf(lstart + buf[0].y, -80.f));
            C = rm[0];
        } else {
            float s0 = 0.f, s1 = 0.f, s2 = 0.f, s3 = 0.f;
            #pragma unroll
            for (int j = 0; j < KK; j += 4) {
                s0 = fmaf(__shfl_sync(FULL, q, j + 0), acol[j + 0], s0);
                s1 = fmaf(__shfl_sync(FULL, q, j + 1), acol[j + 1], s1);
                s2 = fmaf(__shfl_sync(FULL, q, j + 2), acol[j + 2], s2);
                s3 = fmaf(__shfl_sync(FULL, q, j + 3), acol[j + 3], s3);
            }
            float ssum = (s0 + s1) + (s2 + s3);
            float ov = C + rm[u] + buf[u].y + __logf(ssum);
            if (lane < 16) ob[(base + u)*KK + kk] = ov;
            q = ssum * buf[u].x;
            C += rm[u];
        }
    }
    // Renormalize (lanes 16-31 mirror 0-15, so full-warp max == max over k)
    float mq = q;
    #pragma unroll
    for (int off = 16; off; off >>= 1)
        mq = fmaxf(mq, __shfl_xor_sync(FULL, mq, off));
    q = __fdividef(q, mq);
    C += __logf(mq);
}

__global__ void __launch_bounds__(32) scan_kernel(
    const float* __restrict__ start_logits,
    const float* __restrict__ trans,
    float* __restrict__ out)
{
    const unsigned FULL = 0xffffffffu;
    int b = blockIdx.x;
    int lane = threadIdx.x;
    int kk = lane & 15;

    // log_softmax(start_logits)
    float sv = __ldg(start_logits + kk);
    float sm = sv;
    #pragma unroll
    for (int off = 8; off; off >>= 1) sm = fmaxf(sm, __shfl_xor_sync(FULL, sm, off));
    float se = __expf(sv - sm);
    #pragma unroll
    for (int off = 8; off; off >>= 1) se += __shfl_xor_sync(FULL, se, off);
    float lstart = sv - sm - __logf(se);

    // A columns: acol[j] = softmax_row_j(trans)[kk]
    float acol[KK];
    #pragma unroll
    for (int j = 0; j < KK; j++) {
        float v = __ldg(trans + j*KK + kk);
        float mj = v;
        #pragma unroll
        for (int off = 8; off; off >>= 1) mj = fmaxf(mj, __shfl_xor_sync(FULL, mj, off));
        float ej = __expf(v - mj);
        #pragma unroll
        for (int off = 8; off; off >>= 1) ej += __shfl_xor_sync(FULL, ej, off);
        acol[j] = __expf(v - mj - __logf(ej));
    }

    const float2* pf = g_emE + (size_t)b * SS * KK;
    const float*  prm = g_rowmax + b * SS;
    float* ob = out + (size_t)b * SS * KK;

    float q = 0.f, C = 0.f;

    float2 bufA[16], bufB[16];
    float  rmA[16],  rmB[16];

    // Preload block 0
    #pragma unroll
    for (int u = 0; u < 16; u++) {
        bufA[u] = __ldg(pf + u*KK + kk);
        rmA[u]  = __ldg(prm + u);
    }

    const int NB = SS / 16;  // 128 (even)
    for (int blk = 1; blk < NB; blk += 2) {
        #pragma unroll
        for (int u = 0; u < 16; u++) {
            bufB[u] = __ldg(pf + (blk*16 + u)*KK + kk);
            rmB[u]  = __ldg(prm + blk*16 + u);
        }
        scan_block16(bufA, rmA, (blk - 1)*16, q, C, acol, lstart, ob, lane, kk);
        if (blk + 1 < NB) {
            #pragma unroll
            for (int u = 0; u < 16; u++) {
                bufA[u] = __ldg(pf + ((blk + 1)*16 + u)*KK + kk);
                rmA[u]  = __ldg(prm + (blk + 1)*16 + u);
            }
        }
        scan_block16(bufB, rmB, blk*16, q, C, acol, lstart, ob, lane, kk);
    }
}

// ---------------------------------------------------------------------------
extern "C" void kernel_launch(void* const* d_in, const int* in_sizes, int n_in,
                              void* d_out, int out_size) {
    const float* y   = (const float*)d_in[0];
    const float* z   = (const float*)d_in[1];
    const float* st  = (const float*)d_in[2];
    const float* tr  = (const float*)d_in[3];
    const float* mu  = (const float*)d_in[4];
    const float* lv  = (const float*)d_in[5];
    const float* wz  = (const float*)d_in[6];
    const float* ws  = (const float*)d_in[7];
    const float* bd  = (const float*)d_in[8];
    float* out = (float*)d_out;

    setup_kernel<<<1, 1024>>>(lv);
    emissions_kernel<<<NS/SPB, TPB>>>(y, z, wz, ws, bd, mu);
    scan_kernel<<<BB, 32>>>(st, tr, out);
}

// round 3
// speedup vs baseline: 1.7694x; 1.7694x over previous
#include <cuda_runtime.h>

#define BB 16
#define SS 2048
#define KK 16
#define LL 64
#define II 256
#define NS (BB*SS)        // 32768
#define CH 64
#define NC (SS/CH)        // 32 chunks per batch
#define TOTCH (BB*NC)     // 512 chunks total

#define SPB 16            // samples per emissions block
#define TPB 256

#define FULL 0xffffffffu

// Scratch (device globals; no allocation allowed)
__device__ float2 g_emE[NS*KK];        // (E = exp(clamp(em',-80)), em' = em - rowmax)
__device__ float  g_rowmax[NS];
__device__ float  g_invvar[KK*LL];
__device__ float  g_lvsum[KK];
__device__ float  g_ws2[KK];
__device__ float  g_A[KK*KK];          // row-softmaxed transition matrix
__device__ float  g_Rn[TOTCH][KK*KK];  // per-chunk matrix, rows normalized
__device__ float  g_rowlog[TOTCH][KK]; // per-row log scale
__device__ float  g_rmsum[TOTCH];      // sum of rowmax over chunk steps
__device__ float  g_qb[TOTCH][KK];     // boundary q at chunk start (chunks >= 1)
__device__ float  g_Cb[TOTCH];

// ---------------------------------------------------------------------------
// Setup: invvar, per-state logvar sums, ||Ws_k||^2, softmaxed A
// ---------------------------------------------------------------------------
__global__ void setup_kernel(const float* __restrict__ prior_logvar,
                             const float* __restrict__ Ws,
                             const float* __restrict__ trans) {
    int tid = threadIdx.x;
    if (tid < KK*LL) {
        float lv = prior_logvar[tid];
        g_invvar[tid] = 1.0f / (expf(lv) + 1e-8f);
    }
    int w = tid >> 5, lane = tid & 31;
    if (w < KK) {
        // lvsum (row w of logvar, 64 elems)
        float s = 0.f;
        #pragma unroll
        for (int e = 0; e < 2; e++) s += __ldg(prior_logvar + w*LL + lane + 32*e);
        #pragma unroll
        for (int off = 16; off; off >>= 1) s += __shfl_xor_sync(FULL, s, off);
        if (lane == 0) g_lvsum[w] = s;
        // ||Ws_w||^2
        float s2 = 0.f;
        #pragma unroll
        for (int e = 0; e < 8; e++) {
            float v = __ldg(Ws + w*II + lane + 32*e);
            s2 = fmaf(v, v, s2);
        }
        #pragma unroll
        for (int off = 16; off; off >>= 1) s2 += __shfl_xor_sync(FULL, s2, off);
        if (lane == 0) g_ws2[w] = s2;
        // row-softmax of trans (lanes 0..15 active)
        float v = (lane < 16) ? __ldg(trans + w*KK + (lane & 15)) : -1e30f;
        float mx = v;
        #pragma unroll
        for (int off = 8; off; off >>= 1) mx = fmaxf(mx, __shfl_xor_sync(FULL, mx, off));
        float ex = (lane < 16) ? expf(v - mx) : 0.f;
        float se = ex;
        #pragma unroll
        for (int off = 8; off; off >>= 1) se += __shfl_xor_sync(FULL, se, off);
        if (lane < 16) g_A[w*KK + lane] = expf(v - mx - logf(se));
    }
}

// ---------------------------------------------------------------------------
// Emissions
// ---------------------------------------------------------------------------
__global__ void __launch_bounds__(TPB) emissions_kernel(
    const float* __restrict__ Y, const float* __restrict__ Z,
    const float* __restrict__ Wz, const float* __restrict__ Ws,
    const float* __restrict__ bdec, const float* __restrict__ mu)
{
    __shared__ __align__(16) float z_a[LL][SPB];      // [l][s]
    __shared__ __align__(16) float z_b[SPB][LL+4];    // [s][l] padded
    __shared__ __align__(16) float d_sh[SPB][II];
    __shared__ __align__(16) float ws_sh[KK][II+4];

    int tid = threadIdx.x;
    int s0 = blockIdx.x * SPB;

    #pragma unroll
    for (int e = 0; e < (SPB*LL)/TPB; e++) {
        int idx = tid + TPB*e;
        int s = idx >> 6, l = idx & 63;
        float v = Z[(s0 + s)*LL + l];
        z_a[l][s] = v;
        z_b[s][l] = v;
    }
    #pragma unroll
    for (int e = 0; e < (KK*II)/TPB; e++) {
        int idx = tid + TPB*e;
        ws_sh[idx >> 8][idx & 255] = Ws[idx];
    }
    __syncthreads();

    // ---- Phase A: base = b_dec + z @ Wz; d = y - base ----
    {
        float base[SPB];
        float bd = __ldg(bdec + tid);
        #pragma unroll
        for (int s = 0; s < SPB; s++) base[s] = bd;

        #pragma unroll 4
        for (int l = 0; l < LL; l++) {
            float wz = __ldg(Wz + l*II + tid);
            const float4* zr = (const float4*)&z_a[l][0];
            float4 za = zr[0], zb = zr[1], zc = zr[2], zd = zr[3];
            base[0]  = fmaf(za.x, wz, base[0]);
            base[1]  = fmaf(za.y, wz, base[1]);
            base[2]  = fmaf(za.z, wz, base[2]);
            base[3]  = fmaf(za.w, wz, base[3]);
            base[4]  = fmaf(zb.x, wz, base[4]);
            base[5]  = fmaf(zb.y, wz, base[5]);
            base[6]  = fmaf(zb.z, wz, base[6]);
            base[7]  = fmaf(zb.w, wz, base[7]);
            base[8]  = fmaf(zc.x, wz, base[8]);
            base[9]  = fmaf(zc.y, wz, base[9]);
            base[10] = fmaf(zc.z, wz, base[10]);
            base[11] = fmaf(zc.w, wz, base[11]);
            base[12] = fmaf(zd.x, wz, base[12]);
            base[13] = fmaf(zd.y, wz, base[13]);
            base[14] = fmaf(zd.z, wz, base[14]);
            base[15] = fmaf(zd.w, wz, base[15]);
        }
        #pragma unroll
        for (int s = 0; s < SPB; s++) {
            float y = __ldg(Y + (s0 + s)*II + tid);
            d_sh[s][tid] = y - base[s];
        }
    }
    __syncthreads();

    // ---- Phase B: thread (sample, state) ----
    int si = tid >> 4;
    int k  = tid & 15;

    // sumd2 cooperatively: thread covers i = t*16 + k, reduce across 16 lanes
    float sd = 0.f;
    #pragma unroll
    for (int t = 0; t < 16; t++) {
        float dv = d_sh[si][t*16 + k];
        sd = fmaf(dv, dv, sd);
    }
    #pragma unroll
    for (int off = 8; off; off >>= 1) sd += __shfl_xor_sync(FULL, sd, off);

    // dot(d, Ws_k)
    float a0 = 0.f, a1 = 0.f, a2 = 0.f, a3 = 0.f;
    const float4* dr = (const float4*)&d_sh[si][0];
    const float4* wr = (const float4*)&ws_sh[k][0];
    #pragma unroll 8
    for (int i4 = 0; i4 < II/4; i4++) {
        float4 dv = dr[i4], wv = wr[i4];
        a0 = fmaf(dv.x, wv.x, a0);
        a1 = fmaf(dv.y, wv.y, a1);
        a2 = fmaf(dv.z, wv.z, a2);
        a3 = fmaf(dv.w, wv.w, a3);
    }
    float dot = (a0 + a1) + (a2 + a3);
    float accy = sd - 2.f*dot + __ldg(&g_ws2[k]);

    float b0 = 0.f, b1 = 0.f, b2 = 0.f, b3 = 0.f;
    const float4* zr = (const float4*)&z_b[si][0];
    const float4* mr = (const float4*)(mu + k*LL);
    const float4* ir = (const float4*)(g_invvar + k*LL);
    #pragma unroll
    for (int l4 = 0; l4 < LL/4; l4++) {
        float4 zv = zr[l4];
        float4 mv = __ldg(mr + l4);
        float4 iv = __ldg(ir + l4);
        float t0 = zv.x - mv.x; b0 = fmaf(t0*t0, iv.x, b0);
        float t1 = zv.y - mv.y; b1 = fmaf(t1*t1, iv.y, b1);
        float t2 = zv.z - mv.z; b2 = fmaf(t2*t2, iv.z, b2);
        float t3 = zv.w - mv.w; b3 = fmaf(t3*t3, iv.w, b3);
    }
    float accz = (b0 + b1) + (b2 + b3);

    const float LLOG2PI = 117.62413f;  // 64 * log(2*pi)
    float em = -0.5f*accy - 0.5f*(__ldg(&g_lvsum[k]) + accz + LLOG2PI);

    float m = em;
    #pragma unroll
    for (int off = 8; off; off >>= 1)
        m = fmaxf(m, __shfl_xor_sync(FULL, m, off));

    float emp = em - m;
    float E = __expf(fmaxf(emp, -80.f));

    int sample = s0 + si;
    g_emE[sample*KK + k] = make_float2(E, emp);
    if (k == 0) g_rowmax[sample] = m;
}

// ---------------------------------------------------------------------------
// Phase 1: per-chunk matrix product R_c = prod M_t, M_t = A diag(E_t).
// One warp per chunk. Lane (i = lane>>1, half h = lane&1) owns R[i][h*8+kk].
// ---------------------------------------------------------------------------
__global__ void __launch_bounds__(32) phase1_kernel() {
    int c = blockIdx.x;
    int lane = threadIdx.x;
    int b = c / NC, cl = c % NC;
    int i = lane >> 1, h = lane & 1;

    // A columns for this lane's 8 k's
    float a[KK][8];
    #pragma unroll
    for (int j = 0; j < KK; j++)
        #pragma unroll
        for (int kk = 0; kk < 8; kk++)
            a[j][kk] = g_A[j*KK + h*8 + kk];

    float R[8];
    #pragma unroll
    for (int kk = 0; kk < 8; kk++)
        R[kk] = (i == h*8 + kk) ? 1.f : 0.f;

    float rowlog = 0.f, rmsum = 0.f;

    int t0 = b*SS + cl*CH;
    int us = (cl == 0) ? 1 : 0;
    const float* prm = g_rowmax + t0;

    // prefetch E for first step
    float E[8], En[8];
    {
        const float4* p4 = (const float4*)(g_emE + (size_t)(t0 + us)*KK) + h*4;
        float4 q0 = __ldg(p4+0), q1 = __ldg(p4+1), q2 = __ldg(p4+2), q3 = __ldg(p4+3);
        E[0]=q0.x; E[1]=q0.z; E[2]=q1.x; E[3]=q1.z;
        E[4]=q2.x; E[5]=q2.z; E[6]=q3.x; E[7]=q3.z;
    }
    float rmc = __ldg(prm + us), rmn = 0.f;

    for (int u = us; u < CH; u++) {
        // prefetch next step
        if (u + 1 < CH) {
            const float4* p4 = (const float4*)(g_emE + (size_t)(t0 + u + 1)*KK) + h*4;
            float4 q0 = __ldg(p4+0), q1 = __ldg(p4+1), q2 = __ldg(p4+2), q3 = __ldg(p4+3);
            En[0]=q0.x; En[1]=q0.z; En[2]=q1.x; En[3]=q1.z;
            En[4]=q2.x; En[5]=q2.z; En[6]=q3.x; En[7]=q3.z;
            rmn = __ldg(prm + u + 1);
        }
        rmsum += rmc;

        // gather full row i: own 8 + partner 8
        float rp[8];
        #pragma unroll
        for (int j = 0; j < 8; j++) rp[j] = __shfl_xor_sync(FULL, R[j], 1);
        float rlo[8], rhi[8];
        #pragma unroll
        for (int j = 0; j < 8; j++) {
            rlo[j] = h ? rp[j] : R[j];
            rhi[j] = h ? R[j] : rp[j];
        }
        float nw[8];
        #pragma unroll
        for (int kk = 0; kk < 8; kk++) {
            float s0 = 0.f, s1 = 0.f;
            #pragma unroll
            for (int j = 0; j < 8; j++) {
                s0 = fmaf(rlo[j], a[j][kk],   s0);
                s1 = fmaf(rhi[j], a[j+8][kk], s1);
            }
            nw[kk] = (s0 + s1) * E[kk];
        }
        #pragma unroll
        for (int kk = 0; kk < 8; kk++) R[kk] = nw[kk];

        // periodic per-row normalization
        if (((u + 1) & 15) == 0) {
            float mx = R[0];
            #pragma unroll
            for (int kk = 1; kk < 8; kk++) mx = fmaxf(mx, R[kk]);
            mx = fmaxf(mx, __shfl_xor_sync(FULL, mx, 1));
            mx = fmaxf(mx, 1e-37f);
            float inv = __fdividef(1.f, mx);
            #pragma unroll
            for (int kk = 0; kk < 8; kk++) R[kk] *= inv;
            rowlog += __logf(mx);
        }

        #pragma unroll
        for (int kk = 0; kk < 8; kk++) E[kk] = En[kk];
        rmc = rmn;
    }

    #pragma unroll
    for (int kk = 0; kk < 8; kk++)
        g_Rn[c][i*KK + h*8 + kk] = R[kk];
    if (h == 0) g_rowlog[c][i] = rowlog;
    if (lane == 0) g_rmsum[c] = rmsum;
}

// ---------------------------------------------------------------------------
// Phase 2: sequential combine over chunks (one warp per batch), stores
// boundary (q, C) at each chunk start.
// ---------------------------------------------------------------------------
__global__ void __launch_bounds__(32) phase2_kernel(const float* __restrict__ start_logits) {
    int b = blockIdx.x;
    int lane = threadIdx.x;
    int kk = lane & 15;

    // log_softmax(start)
    float sv = __ldg(start_logits + kk);
    float sm = sv;
    #pragma unroll
    for (int off = 8; off; off >>= 1) sm = fmaxf(sm, __shfl_xor_sync(FULL, sm, off));
    float se = __expf(sv - sm);
    #pragma unroll
    for (int off = 8; off; off >>= 1) se += __shfl_xor_sync(FULL, se, off);
    float lstart = sv - sm - __logf(se);

    // init: state after step 0
    float e0 = g_emE[(size_t)(b*SS)*KK + kk].y;
    float t = lstart + e0;
    float m0 = t;
    #pragma unroll
    for (int off = 8; off; off >>= 1) m0 = fmaxf(m0, __shfl_xor_sync(FULL, m0, off));
    float q = __expf(t - m0);
    float C = __ldg(&g_rowmax[b*SS]) + m0;

    // prefetch chunk 0 column
    float col[16], rl, rs;
    {
        int gc = b*NC;
        #pragma unroll
        for (int i = 0; i < 16; i++) col[i] = __ldg(&g_Rn[gc][i*KK + kk]);
        rl = __ldg(&g_rowlog[gc][kk]);
        rs = __ldg(&g_rmsum[gc]);
    }

    for (int c = 0; c < NC; c++) {
        int gc = b*NC + c;
        if (c > 0) {
            if (lane < 16) g_qb[gc][kk] = q;
            if (lane == 0) g_Cb[gc] = C;
        }
        // prefetch next chunk
        float coln[16], rln = 0.f, rsn = 0.f;
        if (c + 1 < NC) {
            #pragma unroll
            for (int i = 0; i < 16; i++) coln[i] = __ldg(&g_Rn[gc+1][i*KK + kk]);
            rln = __ldg(&g_rowlog[gc+1][kk]);
            rsn = __ldg(&g_rmsum[gc+1]);
        }
        // combine: lane index = row i for the weight, = col k for the output
        float ti = ((q > 0.f) ? __logf(q) : -1e30f) + rl;
        float mm = ti;
        #pragma unroll
        for (int off = 8; off; off >>= 1) mm = fmaxf(mm, __shfl_xor_sync(FULL, mm, off));
        float w = __expf(ti - mm);
        float s0 = 0.f, s1 = 0.f, s2 = 0.f, s3 = 0.f;
        #pragma unroll
        for (int j = 0; j < 16; j += 4) {
            s0 = fmaf(__shfl_sync(FULL, w, j + 0), col[j + 0], s0);
            s1 = fmaf(__shfl_sync(FULL, w, j + 1), col[j + 1], s1);
            s2 = fmaf(__shfl_sync(FULL, w, j + 2), col[j + 2], s2);
            s3 = fmaf(__shfl_sync(FULL, w, j + 3), col[j + 3], s3);
        }
        float v = (s0 + s1) + (s2 + s3);
        float mv = v;
        #pragma unroll
        for (int off = 8; off; off >>= 1) mv = fmaxf(mv, __shfl_xor_sync(FULL, mv, off));
        mv = fmaxf(mv, 1e-37f);
        C += rs + mm + __logf(mv);
        q = __fdividef(v, mv);

        #pragma unroll
        for (int i = 0; i < 16; i++) col[i] = coln[i];
        rl = rln; rs = rsn;
    }
}

// ---------------------------------------------------------------------------
// Phase 3: per-chunk vector recursion from stored boundary, writes outputs.
// One warp per chunk, all chunks parallel.
// ---------------------------------------------------------------------------
__global__ void __launch_bounds__(32) phase3_kernel(
    const float* __restrict__ start_logits, float* __restrict__ out)
{
    int c = blockIdx.x;
    int lane = threadIdx.x;
    int b = c / NC, cl = c % NC;
    int kk = lane & 15;

    float acol[KK];
    #pragma unroll
    for (int j = 0; j < KK; j++) acol[j] = __ldg(&g_A[j*KK + kk]);

    const float2* pf = g_emE + (size_t)(b*SS + cl*CH)*KK;
    const float*  prm = g_rowmax + b*SS + cl*CH;
    float* ob = out + (size_t)(b*SS + cl*CH)*KK;

    float2 bufA[16], bufB[16];
    float  rmA[16],  rmB[16];
    #pragma unroll
    for (int u = 0; u < 16; u++) {
        bufA[u] = __ldg(pf + u*KK + kk);
        rmA[u]  = __ldg(prm + u);
    }

    float q, C;
    if (cl == 0) {
        float sv = __ldg(start_logits + kk);
        float sm = sv;
        #pragma unroll
        for (int off = 8; off; off >>= 1) sm = fmaxf(sm, __shfl_xor_sync(FULL, sm, off));
        float se = __expf(sv - sm);
        #pragma unroll
        for (int off = 8; off; off >>= 1) se += __shfl_xor_sync(FULL, se, off);
        float lstart = sv - sm - __logf(se);

        float a0 = lstart + bufA[0].y + rmA[0];
        if (lane < 16) ob[kk] = a0;
        q = __expf(fmaxf(lstart + bufA[0].y, -80.f));
        C = rmA[0];
    } else {
        q = __ldg(&g_qb[c][kk]);
        C = __ldg(&g_Cb[c]);
    }

    const int NSB = CH / 16;  // 4
    for (int sb = 0; sb < NSB; sb++) {
        if (sb + 1 < NSB) {
            #pragma unroll
            for (int u = 0; u < 16; u++) {
                bufB[u] = __ldg(pf + ((sb+1)*16 + u)*KK + kk);
                rmB[u]  = __ldg(prm + (sb+1)*16 + u);
            }
        }
        #pragma unroll
        for (int u = 0; u < 16; u++) {
            if (sb == 0 && u == 0 && cl == 0) continue;  // handled at init
            float s0 = 0.f, s1 = 0.f, s2 = 0.f, s3 = 0.f;
            #pragma unroll
            for (int j = 0; j < KK; j += 4) {
                s0 = fmaf(__shfl_sync(FULL, q, j + 0), acol[j + 0], s0);
                s1 = fmaf(__shfl_sync(FULL, q, j + 1), acol[j + 1], s1);
                s2 = fmaf(__shfl_sync(FULL, q, j + 2), acol[j + 2], s2);
                s3 = fmaf(__shfl_sync(FULL, q, j + 3), acol[j + 3], s3);
            }
            float ssum = (s0 + s1) + (s2 + s3);
            float ov = C + rmA[u] + bufA[u].y + __logf(ssum);
            if (lane < 16) ob[(sb*16 + u)*KK + kk] = ov;
            q = ssum * bufA[u].x;
            C += rmA[u];
        }
        // renormalize q (lanes 16-31 mirror lanes 0-15)
        float mq = q;
        #pragma unroll
        for (int off = 16; off; off >>= 1)
            mq = fmaxf(mq, __shfl_xor_sync(FULL, mq, off));
        q = __fdividef(q, mq);
        C += __logf(mq);

        if (sb + 1 < NSB) {
            #pragma unroll
            for (int u = 0; u < 16; u++) { bufA[u] = bufB[u]; rmA[u] = rmB[u]; }
        }
    }
}

// ---------------------------------------------------------------------------
extern "C" void kernel_launch(void* const* d_in, const int* in_sizes, int n_in,
                              void* d_out, int out_size) {
    const float* y   = (const float*)d_in[0];
    const float* z   = (const float*)d_in[1];
    const float* st  = (const float*)d_in[2];
    const float* tr  = (const float*)d_in[3];
    const float* mu  = (const float*)d_in[4];
    const float* lv  = (const float*)d_in[5];
    const float* wz  = (const float*)d_in[6];
    const float* ws  = (const float*)d_in[7];
    const float* bd  = (const float*)d_in[8];
    float* out = (float*)d_out;

    setup_kernel<<<1, 1024>>>(lv, ws, tr);
    emissions_kernel<<<NS/SPB, TPB>>>(y, z, wz, ws, bd, mu);
    phase1_kernel<<<TOTCH, 32>>>();
    phase2_kernel<<<BB, 32>>>(st);
    phase3_kernel<<<TOTCH, 32>>>(st, out);
}